// round 2
// baseline (speedup 1.0000x reference)
#include <cuda_runtime.h>
#include <cuda_bf16.h>

// Problem constants (fixed by reference config)
#define OCn   16
#define IDIM  72
#define Pn    5
#define IHc   32
#define IWc   32
#define ICc   8

// Per-neuron packed constants: 28 floats = 7 float4
//  w[0]=l2, w[1]=sqrt(l2), w[2..6]=z[5], w[7..11]=alpha[5], w[12..26]=Linv(15, lower-tri), w[27]=pad
__device__ float4 g_const[OCn * IDIM * 7];

__device__ __forceinline__ float ex2f(float x) {
    float r;
    asm("ex2.approx.ftz.f32 %0, %1;" : "=f"(r) : "f"(x));
    return r;
}

// ---------------------------------------------------------------------------
// Precompute kernel: per-neuron GP solve in fp64 (1152 neurons, tiny)
// ---------------------------------------------------------------------------
__global__ void precompute_kernel(const float* __restrict__ z,
                                  const float* __restrict__ h,
                                  const float* __restrict__ raw_l) {
    int idx = blockIdx.x * blockDim.x + threadIdx.x;
    if (idx >= OCn * IDIM) return;

    double raw = (double)raw_l[idx];
    double l   = log1p(exp(raw));          // softplus
    double l2  = l * l;

    double zv[Pn], hv[Pn];
#pragma unroll
    for (int p = 0; p < Pn; p++) {
        zv[p] = (double)z[idx * Pn + p];
        hv[p] = (double)h[idx * Pn + p];
    }

    double K[Pn][Pn];
#pragma unroll
    for (int p = 0; p < Pn; p++)
#pragma unroll
        for (int q = 0; q < Pn; q++) {
            double dz = zv[p] - zv[q];
            K[p][q] = exp(-0.5 * dz * dz / l2);
        }
#pragma unroll
    for (int p = 0; p < Pn; p++) K[p][p] += 1e-4;   // jitter

    // Cholesky K = L L^T (lower)
    double L[Pn][Pn];
#pragma unroll
    for (int j = 0; j < Pn; j++) {
        double s = K[j][j];
        for (int k = 0; k < j; k++) s -= L[j][k] * L[j][k];
        double ljj = sqrt(s);
        L[j][j] = ljj;
        for (int i = j + 1; i < Pn; i++) {
            double t = K[i][j];
            for (int k = 0; k < j; k++) t -= L[i][k] * L[j][k];
            L[i][j] = t / ljj;
        }
    }

    // Linv = L^{-1} (lower-triangular)
    double Li[Pn][Pn];
#pragma unroll
    for (int j = 0; j < Pn; j++) {
        Li[j][j] = 1.0 / L[j][j];
        for (int i = j + 1; i < Pn; i++) {
            double s = 0.0;
            for (int k = j; k < i; k++) s += L[i][k] * Li[k][j];
            Li[i][j] = -s / L[i][i];
        }
    }

    // alpha = K^{-1} h via two triangular solves
    double y[Pn], a[Pn];
#pragma unroll
    for (int i = 0; i < Pn; i++) {
        double s = hv[i];
        for (int k = 0; k < i; k++) s -= L[i][k] * y[k];
        y[i] = s / L[i][i];
    }
#pragma unroll
    for (int i = Pn - 1; i >= 0; i--) {
        double s = y[i];
        for (int k = i + 1; k < Pn; k++) s -= L[k][i] * a[k];
        a[i] = s / L[i][i];
    }

    float w[28];
    w[0] = (float)l2;
    w[1] = (float)sqrt(l2);
#pragma unroll
    for (int p = 0; p < Pn; p++) { w[2 + p] = (float)zv[p]; w[7 + p] = (float)a[p]; }
    int t = 12;
#pragma unroll
    for (int p = 0; p < Pn; p++)
        for (int j = 0; j <= p; j++) w[t++] = (float)Li[p][j];
    w[27] = 0.0f;

    float4* dst = &g_const[idx * 7];
#pragma unroll
    for (int k = 0; k < 7; k++)
        dst[k] = make_float4(w[4 * k + 0], w[4 * k + 1], w[4 * k + 2], w[4 * k + 3]);
}

// ---------------------------------------------------------------------------
// Main kernel: blockIdx.y = output channel o (constants uniform per block,
// staged in smem -> warp-broadcast LDS). 256 threads = 256 consecutive rows.
// ---------------------------------------------------------------------------
__device__ __forceinline__ void accum_neuron(const float* __restrict__ w,
                                             float mu, float s2,
                                             float& mean, float& qkq) {
    float d  = w[0] + s2;
    float rd = rsqrtf(d);
    float s  = w[1] * rd;
    float e  = rd * rd * (-0.7213475204444817f);   // -0.5 * log2(e) / d

    float f0 = mu - w[2]; float q0 = s * ex2f(f0 * f0 * e);
    float f1 = mu - w[3]; float q1 = s * ex2f(f1 * f1 * e);
    float f2 = mu - w[4]; float q2 = s * ex2f(f2 * f2 * e);
    float f3 = mu - w[5]; float q3 = s * ex2f(f3 * f3 * e);
    float f4 = mu - w[6]; float q4 = s * ex2f(f4 * f4 * e);

    mean = fmaf(q0, w[7],  mean);
    mean = fmaf(q1, w[8],  mean);
    mean = fmaf(q2, w[9],  mean);
    mean = fmaf(q3, w[10], mean);
    mean = fmaf(q4, w[11], mean);

    // u = Linv * q  (lower-triangular),  qkq += |u|^2
    float u0 = w[12] * q0;
    float u1 = fmaf(w[13], q0, w[14] * q1);
    float u2 = fmaf(w[15], q0, fmaf(w[16], q1, w[17] * q2));
    float u3 = fmaf(w[18], q0, fmaf(w[19], q1, fmaf(w[20], q2, w[21] * q3)));
    float u4 = fmaf(w[22], q0, fmaf(w[23], q1, fmaf(w[24], q2, fmaf(w[25], q3, w[26] * q4))));

    qkq = fmaf(u0, u0, qkq);
    qkq = fmaf(u1, u1, qkq);
    qkq = fmaf(u2, u2, qkq);
    qkq = fmaf(u3, u3, qkq);
    qkq = fmaf(u4, u4, qkq);
}

__global__ void __launch_bounds__(256) gp_main(const float* __restrict__ xm,
                                               const float* __restrict__ xv,
                                               float* __restrict__ out,
                                               int var_off) {
    __shared__ float4 sc[IDIM * 7];       // 8064 B: this o's packed constants

    int o   = blockIdx.y;
    int row = blockIdx.x * 256 + threadIdx.x;

    // stage constants (uniform per block) into smem
    {
        const float4* src = g_const + o * (IDIM * 7);
        for (int k = threadIdx.x; k < IDIM * 7; k += 256)
            sc[k] = src[k];
    }
    __syncthreads();

    int ow = row & 31, oh = (row >> 5) & 31, n = row >> 10;

    float m = 0.f, kq = 0.f;
    const float4* cp = sc;

    for (int c = 0; c < ICc; c++) {
#pragma unroll
        for (int kh = 0; kh < 3; kh++) {
#pragma unroll
            for (int kw = 0; kw < 3; kw++) {
                const float* w = (const float*)cp;   // warp-uniform LDS (broadcast)
                cp += 7;

                int ih = oh + kh - 1, iw = ow + kw - 1;
                bool v = ((unsigned)ih < (unsigned)IHc) & ((unsigned)iw < (unsigned)IWc);
                int a = (((n * IHc + ih) * IWc) + iw) * ICc + c;

                float mu = v ? __ldg(xm + a) : 0.f;
                float s2 = v ? __ldg(xv + a) : 0.f;

                accum_neuron(w, mu, s2, m, kq);
            }
        }
    }

    // outputs: mean block then var block, each [N,OH,OW,OC]
    out[row * OCn + o] = m;
    out[var_off + row * OCn + o] = fmaxf((float)IDIM - kq, 1e-6f);
}

// ---------------------------------------------------------------------------
extern "C" void kernel_launch(void* const* d_in, const int* in_sizes, int n_in,
                              void* d_out, int out_size) {
    const float* xm = (const float*)d_in[0];   // x_mean [N,32,32,8]
    const float* xv = (const float*)d_in[1];   // x_var  [N,32,32,8]
    const float* z  = (const float*)d_in[2];   // [16,72,5]
    const float* h  = (const float*)d_in[3];   // [16,72,5]
    const float* rl = (const float*)d_in[4];   // [16,72]

    precompute_kernel<<<(OCn * IDIM + 127) / 128, 128>>>(z, h, rl);

    int rows = in_sizes[0] / ICc;              // N * OH * OW (stride1, pad1 => OH=IH)
    int var_off = rows * OCn;
    dim3 grid(rows / 256, OCn);
    gp_main<<<grid, 256>>>(xm, xv, (float*)d_out, var_off);
}

// round 12
// speedup vs baseline: 1.6704x; 1.6704x over previous
#include <cuda_runtime.h>
#include <cuda_bf16.h>

// Problem constants (fixed by reference config)
#define OCn   16
#define IDIM  72
#define Pn    5
#define IHc   32
#define IWc   32
#define ICc   8

// Per-neuron packed constants: 28 floats = 7 float4
//  [0]=l2, [1]=sqrt(l2), [2..6]=z[5], [7..11]=alpha[5], [12..26]=Linv(15, lower-tri), [27]=pad
__device__ float4 g_const[OCn * IDIM * 7];

__device__ __forceinline__ float ex2f(float x) {
    float r;
    asm("ex2.approx.ftz.f32 %0, %1;" : "=f"(r) : "f"(x));
    return r;
}

// ---------------------------------------------------------------------------
// Precompute: per-neuron GP solve. K entries via fp32 exp (fp64 argument),
// Cholesky + triangular solves in fp64 (conditioning-sensitive part).
// ---------------------------------------------------------------------------
__global__ void precompute_kernel(const float* __restrict__ z,
                                  const float* __restrict__ h,
                                  const float* __restrict__ raw_l) {
    int idx = blockIdx.x * blockDim.x + threadIdx.x;
    if (idx >= OCn * IDIM) return;

    double raw = (double)raw_l[idx];
    double l   = log1p(exp(raw));          // softplus (one fp64 exp per neuron)
    double l2  = l * l;
    double inv2l2 = -0.5 / l2;

    double zv[Pn], hv[Pn];
#pragma unroll
    for (int p = 0; p < Pn; p++) {
        zv[p] = (double)z[idx * Pn + p];
        hv[p] = (double)h[idx * Pn + p];
    }

    double K[Pn][Pn];
#pragma unroll
    for (int p = 0; p < Pn; p++) K[p][p] = 1.0 + 1e-4;
#pragma unroll
    for (int p = 1; p < Pn; p++)
        for (int q = 0; q < p; q++) {
            double dz = zv[p] - zv[q];
            double v  = (double)expf((float)(dz * dz * inv2l2));  // fp32 exp, fp64 arg
            K[p][q] = v; K[q][p] = v;
        }

    // Cholesky K = L L^T (lower), fp64
    double L[Pn][Pn];
#pragma unroll
    for (int j = 0; j < Pn; j++) {
        double s = K[j][j];
        for (int k = 0; k < j; k++) s -= L[j][k] * L[j][k];
        double ljj = sqrt(s);
        L[j][j] = ljj;
        double rinv = 1.0 / ljj;
        for (int i = j + 1; i < Pn; i++) {
            double t = K[i][j];
            for (int k = 0; k < j; k++) t -= L[i][k] * L[j][k];
            L[i][j] = t * rinv;
        }
    }

    // Linv = L^{-1} (lower-triangular)
    double Li[Pn][Pn];
#pragma unroll
    for (int j = 0; j < Pn; j++) {
        Li[j][j] = 1.0 / L[j][j];
        for (int i = j + 1; i < Pn; i++) {
            double s = 0.0;
            for (int k = j; k < i; k++) s += L[i][k] * Li[k][j];
            Li[i][j] = -s / L[i][i];
        }
    }

    // alpha = K^{-1} h via two triangular solves
    double y[Pn], a[Pn];
#pragma unroll
    for (int i = 0; i < Pn; i++) {
        double s = hv[i];
        for (int k = 0; k < i; k++) s -= L[i][k] * y[k];
        y[i] = s / L[i][i];
    }
#pragma unroll
    for (int i = Pn - 1; i >= 0; i--) {
        double s = y[i];
        for (int k = i + 1; k < Pn; k++) s -= L[k][i] * a[k];
        a[i] = s / L[i][i];
    }

    float w[28];
    w[0] = (float)l2;
    w[1] = (float)sqrt(l2);
#pragma unroll
    for (int p = 0; p < Pn; p++) { w[2 + p] = (float)zv[p]; w[7 + p] = (float)a[p]; }
    int t = 12;
#pragma unroll
    for (int p = 0; p < Pn; p++)
        for (int j = 0; j <= p; j++) w[t++] = (float)Li[p][j];
    w[27] = 0.0f;

    float4* dst = &g_const[idx * 7];
#pragma unroll
    for (int k = 0; k < 7; k++)
        dst[k] = make_float4(w[4 * k + 0], w[4 * k + 1], w[4 * k + 2], w[4 * k + 3]);
}

// ---------------------------------------------------------------------------
// Main kernel: blockIdx.y = output channel o. 128 threads x 2 rows each.
// Taps (kh,kw) outer loop (not unrolled); channels inner (unrolled, LDG.128 x-gather).
// Constants staged in smem permuted to (tap, c) order; warp-uniform LDS.128 reads.
// ---------------------------------------------------------------------------
#define KLOG2E (-0.7213475204444817f)   // -0.5 * log2(e)

__global__ void __launch_bounds__(128) gp_main(const float* __restrict__ xm,
                                               const float* __restrict__ xv,
                                               float* __restrict__ out,
                                               int var_off) {
    __shared__ float4 sc[IDIM * 7];     // 8064 B, permuted: ((tap*8 + c)*7 + k)

    const int o   = blockIdx.y;
    const int tid = threadIdx.x;
    __builtin_assume(tid >= 0 && tid < 128);

    // stage + permute constants: src neuron i = c*9 + tap  ->  dst = tap*8 + c
    for (int k = tid; k < IDIM * 7; k += 128) {
        int neuron = k / 7, r = k % 7;
        int tap = neuron >> 3, c = neuron & 7;
        sc[k] = g_const[(o * IDIM + c * 9 + tap) * 7 + r];
    }
    __syncthreads();

    const int row0 = blockIdx.x * 256 + tid;
    const int row1 = row0 + 128;

    const int ow0 = row0 & 31, oh0 = (row0 >> 5) & 31, n0 = row0 >> 10;
    const int ow1 = row1 & 31, oh1 = (row1 >> 5) & 31, n1 = row1 >> 10;

    float m0 = 0.f, q0s = 0.f, m1 = 0.f, q1s = 0.f;
    const float4 f4z = make_float4(0.f, 0.f, 0.f, 0.f);

    for (int tap = 0; tap < 9; tap++) {
        int kh = tap / 3, kw = tap - kh * 3;

        int ih0 = oh0 + kh - 1, iw0 = ow0 + kw - 1;
        int ih1 = oh1 + kh - 1, iw1 = ow1 + kw - 1;
        bool v0 = ((unsigned)ih0 < (unsigned)IHc) & ((unsigned)iw0 < (unsigned)IWc);
        bool v1 = ((unsigned)ih1 < (unsigned)IHc) & ((unsigned)iw1 < (unsigned)IWc);
        int a0 = (((n0 * IHc + ih0) * IWc) + iw0) * ICc;    // float index, 32B aligned
        int a1 = (((n1 * IHc + ih1) * IWc) + iw1) * ICc;

        // vectorized x-gather: 8 channels = 2 x LDG.128 per tensor per row
        float mu0[8], s20[8], mu1[8], s21[8];
        *(float4*)&mu0[0] = v0 ? __ldg((const float4*)(xm + a0))     : f4z;
        *(float4*)&mu0[4] = v0 ? __ldg((const float4*)(xm + a0) + 1) : f4z;
        *(float4*)&s20[0] = v0 ? __ldg((const float4*)(xv + a0))     : f4z;
        *(float4*)&s20[4] = v0 ? __ldg((const float4*)(xv + a0) + 1) : f4z;
        *(float4*)&mu1[0] = v1 ? __ldg((const float4*)(xm + a1))     : f4z;
        *(float4*)&mu1[4] = v1 ? __ldg((const float4*)(xm + a1) + 1) : f4z;
        *(float4*)&s21[0] = v1 ? __ldg((const float4*)(xv + a1))     : f4z;
        *(float4*)&s21[4] = v1 ? __ldg((const float4*)(xv + a1) + 1) : f4z;

        const float4* wbase = sc + tap * 8 * 7;

#pragma unroll
        for (int c = 0; c < 8; c++) {
            // 7 x LDS.128, warp-uniform (broadcast)
            float4 w0 = wbase[c * 7 + 0], w1 = wbase[c * 7 + 1], w2 = wbase[c * 7 + 2];
            float4 w3 = wbase[c * 7 + 3], w4 = wbase[c * 7 + 4], w5 = wbase[c * 7 + 5];
            float4 w6 = wbase[c * 7 + 6];

            const float l2 = w0.x, sl = w0.y;
            const float z0 = w0.z, z1 = w0.w, z2 = w1.x, z3 = w1.y, z4 = w1.z;
            const float a0c = w1.w, a1c = w2.x, a2c = w2.y, a3c = w2.z, a4c = w2.w;
            const float L00 = w3.x, L10 = w3.y, L11 = w3.z, L20 = w3.w;
            const float L21 = w4.x, L22 = w4.y, L30 = w4.z, L31 = w4.w;
            const float L32 = w5.x, L33 = w5.y, L40 = w5.z, L41 = w5.w;
            const float L42 = w6.x, L43 = w6.y, L44 = w6.z;

            auto acc = [&](float mu, float s2, float& M, float& Q) {
                float d  = l2 + s2;
                float rd = rsqrtf(d);
                float s  = sl * rd;
                float e  = rd * rd * KLOG2E;
                float f0 = mu - z0, f1 = mu - z1, f2 = mu - z2, f3 = mu - z3, f4 = mu - z4;
                float E0 = ex2f(f0 * f0 * e);
                float E1 = ex2f(f1 * f1 * e);
                float E2 = ex2f(f2 * f2 * e);
                float E3 = ex2f(f3 * f3 * e);
                float E4 = ex2f(f4 * f4 * e);

                float dt = E0 * a0c;
                dt = fmaf(E1, a1c, dt); dt = fmaf(E2, a2c, dt);
                dt = fmaf(E3, a3c, dt); dt = fmaf(E4, a4c, dt);
                M = fmaf(s, dt, M);

                float u0 = L00 * E0;
                float u1 = fmaf(L10, E0, L11 * E1);
                float u2 = fmaf(L20, E0, fmaf(L21, E1, L22 * E2));
                float u3 = fmaf(L30, E0, fmaf(L31, E1, fmaf(L32, E2, L33 * E3)));
                float u4 = fmaf(L40, E0, fmaf(L41, E1, fmaf(L42, E2, fmaf(L43, E3, L44 * E4))));

                float nn = u0 * u0;
                nn = fmaf(u1, u1, nn); nn = fmaf(u2, u2, nn);
                nn = fmaf(u3, u3, nn); nn = fmaf(u4, u4, nn);
                Q = fmaf(s * s, nn, Q);
            };

            acc(mu0[c], s20[c], m0, q0s);
            acc(mu1[c], s21[c], m1, q1s);
        }
    }

    // outputs: mean block then var block, each [N,OH,OW,OC]
    out[row0 * OCn + o] = m0;
    out[row1 * OCn + o] = m1;
    out[var_off + row0 * OCn + o] = fmaxf((float)IDIM - q0s, 1e-6f);
    out[var_off + row1 * OCn + o] = fmaxf((float)IDIM - q1s, 1e-6f);
}

// ---------------------------------------------------------------------------
extern "C" void kernel_launch(void* const* d_in, const int* in_sizes, int n_in,
                              void* d_out, int out_size) {
    const float* xm = (const float*)d_in[0];   // x_mean [N,32,32,8]
    const float* xv = (const float*)d_in[1];   // x_var  [N,32,32,8]
    const float* z  = (const float*)d_in[2];   // [16,72,5]
    const float* h  = (const float*)d_in[3];   // [16,72,5]
    const float* rl = (const float*)d_in[4];   // [16,72]

    precompute_kernel<<<(OCn * IDIM + 63) / 64, 64>>>(z, h, rl);

    int rows = in_sizes[0] / ICc;              // N * OH * OW
    int var_off = rows * OCn;
    dim3 grid(rows / 256, OCn);
    gp_main<<<grid, 128>>>(xm, xv, (float*)d_out, var_off);
}

// round 13
// speedup vs baseline: 1.9431x; 1.1633x over previous
#include <cuda_runtime.h>
#include <cuda_bf16.h>

// Problem constants (fixed by reference config)
#define OCn   16
#define IDIM  72
#define Pn    5
#define IHc   32
#define IWc   32
#define ICc   8

// Per-neuron packed constants: 28 floats = 7 float4
//  [0]=l2, [1]=sqrt(l2), [2..6]=z[5], [7..11]=alpha[5], [12..26]=Linv(15, lower-tri), [27]=pad
__device__ float4 g_const[OCn * IDIM * 7];

__device__ __forceinline__ float ex2f(float x) {
    float r;
    asm("ex2.approx.ftz.f32 %0, %1;" : "=f"(r) : "f"(x));
    return r;
}

// ---------------------------------------------------------------------------
// Precompute: per-neuron GP solve. K entries via fp32 exp (fp64 argument),
// Cholesky + triangular solves in fp64. Diagonal reciprocals precomputed
// once (5 divs) and reused everywhere -> shorter fp64 latency chain.
// ---------------------------------------------------------------------------
__global__ void precompute_kernel(const float* __restrict__ z,
                                  const float* __restrict__ h,
                                  const float* __restrict__ raw_l) {
    int idx = blockIdx.x * blockDim.x + threadIdx.x;
    if (idx >= OCn * IDIM) return;

    double raw = (double)raw_l[idx];
    double l   = log1p(exp(raw));          // softplus (one fp64 exp per neuron)
    double l2  = l * l;
    double inv2l2 = -0.5 / l2;

    double zv[Pn], hv[Pn];
#pragma unroll
    for (int p = 0; p < Pn; p++) {
        zv[p] = (double)z[idx * Pn + p];
        hv[p] = (double)h[idx * Pn + p];
    }

    double K[Pn][Pn];
#pragma unroll
    for (int p = 0; p < Pn; p++) K[p][p] = 1.0 + 1e-4;
#pragma unroll
    for (int p = 1; p < Pn; p++)
        for (int q = 0; q < p; q++) {
            double dz = zv[p] - zv[q];
            double v  = (double)expf((float)(dz * dz * inv2l2));  // fp32 exp, fp64 arg
            K[p][q] = v; K[q][p] = v;
        }

    // Cholesky K = L L^T (lower), fp64; idiag[j] = 1/L[j][j] computed once
    double L[Pn][Pn], idiag[Pn];
#pragma unroll
    for (int j = 0; j < Pn; j++) {
        double s = K[j][j];
        for (int k = 0; k < j; k++) s -= L[j][k] * L[j][k];
        double ljj = sqrt(s);
        L[j][j] = ljj;
        double rinv = 1.0 / ljj;
        idiag[j] = rinv;
        for (int i = j + 1; i < Pn; i++) {
            double t = K[i][j];
            for (int k = 0; k < j; k++) t -= L[i][k] * L[j][k];
            L[i][j] = t * rinv;
        }
    }

    // Linv = L^{-1} (lower-triangular) via reciprocal multiplies
    double Li[Pn][Pn];
#pragma unroll
    for (int j = 0; j < Pn; j++) {
        Li[j][j] = idiag[j];
        for (int i = j + 1; i < Pn; i++) {
            double s = 0.0;
            for (int k = j; k < i; k++) s += L[i][k] * Li[k][j];
            Li[i][j] = -s * idiag[i];
        }
    }

    // alpha = K^{-1} h via two triangular solves (reciprocal multiplies)
    double y[Pn], a[Pn];
#pragma unroll
    for (int i = 0; i < Pn; i++) {
        double s = hv[i];
        for (int k = 0; k < i; k++) s -= L[i][k] * y[k];
        y[i] = s * idiag[i];
    }
#pragma unroll
    for (int i = Pn - 1; i >= 0; i--) {
        double s = y[i];
        for (int k = i + 1; k < Pn; k++) s -= L[k][i] * a[k];
        a[i] = s * idiag[i];
    }

    float w[28];
    w[0] = (float)l2;
    w[1] = (float)sqrt(l2);
#pragma unroll
    for (int p = 0; p < Pn; p++) { w[2 + p] = (float)zv[p]; w[7 + p] = (float)a[p]; }
    int t = 12;
#pragma unroll
    for (int p = 0; p < Pn; p++)
        for (int j = 0; j <= p; j++) w[t++] = (float)Li[p][j];
    w[27] = 0.0f;

    float4* dst = &g_const[idx * 7];
#pragma unroll
    for (int k = 0; k < 7; k++)
        dst[k] = make_float4(w[4 * k + 0], w[4 * k + 1], w[4 * k + 2], w[4 * k + 3]);
}

// ---------------------------------------------------------------------------
// Main kernel: blockIdx.y = output channel o, 1 row per thread (RT=1).
// Grid 1024x16 -> ~6.9 blocks/SM in one resident wave (occ ~43%), fixing the
// grid-limited occ=18.2% measured with RT=2 at 512 blocks.
// Taps (kh,kw) outer loop; channels inner (unrolled, 2xLDG.128 x-gather).
// Constants staged in smem permuted to (tap, c) order; warp-uniform LDS.128.
// ---------------------------------------------------------------------------
#define KLOG2E (-0.7213475204444817f)   // -0.5 * log2(e)

__global__ void __launch_bounds__(128) gp_main(const float* __restrict__ xm,
                                               const float* __restrict__ xv,
                                               float* __restrict__ out,
                                               int var_off) {
    __shared__ float4 sc[IDIM * 7];     // 8064 B, permuted: ((tap*8 + c)*7 + k)

    const int o   = blockIdx.y;
    const int tid = threadIdx.x;
    __builtin_assume(tid >= 0 && tid < 128);

    // stage + permute constants: src neuron i = c*9 + tap  ->  dst = tap*8 + c
    for (int k = tid; k < IDIM * 7; k += 128) {
        int neuron = k / 7, r = k % 7;
        int tap = neuron >> 3, c = neuron & 7;
        sc[k] = g_const[(o * IDIM + c * 9 + tap) * 7 + r];
    }
    __syncthreads();

    const int row = blockIdx.x * 128 + tid;
    const int ow = row & 31, oh = (row >> 5) & 31, n = row >> 10;

    float m0 = 0.f, q0s = 0.f;
    const float4 f4z = make_float4(0.f, 0.f, 0.f, 0.f);

    for (int tap = 0; tap < 9; tap++) {
        int kh = tap / 3, kw = tap - kh * 3;

        int ih = oh + kh - 1, iw = ow + kw - 1;
        bool v = ((unsigned)ih < (unsigned)IHc) & ((unsigned)iw < (unsigned)IWc);
        int a = (((n * IHc + ih) * IWc) + iw) * ICc;     // float index, 32B aligned

        // vectorized x-gather: 8 channels = 2 x LDG.128 per tensor
        float mu[8], s2[8];
        *(float4*)&mu[0] = v ? __ldg((const float4*)(xm + a))     : f4z;
        *(float4*)&mu[4] = v ? __ldg((const float4*)(xm + a) + 1) : f4z;
        *(float4*)&s2[0] = v ? __ldg((const float4*)(xv + a))     : f4z;
        *(float4*)&s2[4] = v ? __ldg((const float4*)(xv + a) + 1) : f4z;

        const float4* wbase = sc + tap * 8 * 7;

#pragma unroll
        for (int c = 0; c < 8; c++) {
            // 7 x LDS.128, warp-uniform (broadcast)
            float4 w0 = wbase[c * 7 + 0], w1 = wbase[c * 7 + 1], w2 = wbase[c * 7 + 2];
            float4 w3 = wbase[c * 7 + 3], w4 = wbase[c * 7 + 4], w5 = wbase[c * 7 + 5];
            float4 w6 = wbase[c * 7 + 6];

            const float l2 = w0.x, sl = w0.y;
            const float z0 = w0.z, z1 = w0.w, z2 = w1.x, z3 = w1.y, z4 = w1.z;
            const float a0c = w1.w, a1c = w2.x, a2c = w2.y, a3c = w2.z, a4c = w2.w;
            const float L00 = w3.x, L10 = w3.y, L11 = w3.z, L20 = w3.w;
            const float L21 = w4.x, L22 = w4.y, L30 = w4.z, L31 = w4.w;
            const float L32 = w5.x, L33 = w5.y, L40 = w5.z, L41 = w5.w;
            const float L42 = w6.x, L43 = w6.y, L44 = w6.z;

            float d  = l2 + s2[c];
            float rd = rsqrtf(d);
            float s  = sl * rd;
            float e  = rd * rd * KLOG2E;
            float muc = mu[c];
            float f0 = muc - z0, f1 = muc - z1, f2 = muc - z2, f3 = muc - z3, f4 = muc - z4;
            float E0 = ex2f(f0 * f0 * e);
            float E1 = ex2f(f1 * f1 * e);
            float E2 = ex2f(f2 * f2 * e);
            float E3 = ex2f(f3 * f3 * e);
            float E4 = ex2f(f4 * f4 * e);

            float dt = E0 * a0c;
            dt = fmaf(E1, a1c, dt); dt = fmaf(E2, a2c, dt);
            dt = fmaf(E3, a3c, dt); dt = fmaf(E4, a4c, dt);
            m0 = fmaf(s, dt, m0);

            float u0 = L00 * E0;
            float u1 = fmaf(L10, E0, L11 * E1);
            float u2 = fmaf(L20, E0, fmaf(L21, E1, L22 * E2));
            float u3 = fmaf(L30, E0, fmaf(L31, E1, fmaf(L32, E2, L33 * E3)));
            float u4 = fmaf(L40, E0, fmaf(L41, E1, fmaf(L42, E2, fmaf(L43, E3, L44 * E4))));

            float nn = u0 * u0;
            nn = fmaf(u1, u1, nn); nn = fmaf(u2, u2, nn);
            nn = fmaf(u3, u3, nn); nn = fmaf(u4, u4, nn);
            q0s = fmaf(s * s, nn, q0s);
        }
    }

    // outputs: mean block then var block, each [N,OH,OW,OC]
    out[row * OCn + o] = m0;
    out[var_off + row * OCn + o] = fmaxf((float)IDIM - q0s, 1e-6f);
}

// ---------------------------------------------------------------------------
extern "C" void kernel_launch(void* const* d_in, const int* in_sizes, int n_in,
                              void* d_out, int out_size) {
    const float* xm = (const float*)d_in[0];   // x_mean [N,32,32,8]
    const float* xv = (const float*)d_in[1];   // x_var  [N,32,32,8]
    const float* z  = (const float*)d_in[2];   // [16,72,5]
    const float* h  = (const float*)d_in[3];   // [16,72,5]
    const float* rl = (const float*)d_in[4];   // [16,72]

    precompute_kernel<<<(OCn * IDIM + 63) / 64, 64>>>(z, h, rl);

    int rows = in_sizes[0] / ICc;              // N * OH * OW
    int var_off = rows * OCn;
    dim3 grid(rows / 128, OCn);                // 1024 x 16 blocks
    gp_main<<<grid, 128>>>(xm, xv, (float*)d_out, var_off);
}